// round 7
// baseline (speedup 1.0000x reference)
#include <cuda_runtime.h>
#include <cuda_fp16.h>
#include <math.h>
#include <stdint.h>

#define N_NODES   100000
#define N_EDGES   3200000
#define NE_TOT    (N_EDGES + N_NODES)   // edges + self loops
#define IN_C      256
#define OUT_C     64
#define NEG_SLOPE 0.2f

#define SCAN_BS   1024
#define SCAN_NB   ((N_NODES + SCAN_BS - 1) / SCAN_BS)   // 98

#define GEMM_BLOCKS  782                 // ceil(100000 / 128)
#define HIST_BLOCKS  1568
#define FUSED_BLOCKS (GEMM_BLOCKS + HIST_BLOCKS)

// ---------------- scratch (static device globals; no allocation) ----------------
__device__ __half2 g_hh[(size_t)N_NODES * 32];    // 12.8 MB: h in fp16 (32 half2/row)
__device__ float   g_si[N_NODES];                 // h @ a_i
__device__ float   g_sj[N_NODES];                 // h @ a_j
__device__ int     g_cnt[N_NODES];                // histogram by col -> place cursor
__device__ int     g_start[N_NODES + 1];          // CSR offsets
__device__ int     g_bsum[SCAN_NB];               // block sums for scan
__device__ int     g_csri[NE_TOT];                // CSR: source row per slot

// ---------------- helpers ----------------
__device__ __forceinline__ void split2(float e, float o, uint32_t& hi, uint32_t& lo) {
    asm("cvt.rn.bf16x2.f32 %0, %1, %2;" : "=r"(hi) : "f"(o), "f"(e));
    float fe = __uint_as_float(hi << 16);
    float fo = __uint_as_float(hi & 0xffff0000u);
    asm("cvt.rn.bf16x2.f32 %0, %1, %2;" : "=r"(lo) : "f"(o - fo), "f"(e - fe));
}

__device__ __forceinline__ void mma_bf16(float* d, const uint32_t* a,
                                         uint32_t b0, uint32_t b1) {
    asm volatile(
        "mma.sync.aligned.m16n8k16.row.col.f32.bf16.bf16.f32 "
        "{%0,%1,%2,%3}, {%4,%5,%6,%7}, {%8,%9}, {%0,%1,%2,%3};"
        : "+f"(d[0]), "+f"(d[1]), "+f"(d[2]), "+f"(d[3])
        : "r"(a[0]), "r"(a[1]), "r"(a[2]), "r"(a[3]), "r"(b0), "r"(b1));
}

// ---------------- kernel: init (self-loop pre-counted in histogram) ----------------
__global__ void zero_kernel() {
    int i = blockIdx.x * blockDim.x + threadIdx.x;
    if (i < N_NODES) g_cnt[i] = 1;
}

// ---------------- fused kernel: bf16-split TC GEMM + scores | histogram ----------
__global__ __launch_bounds__(256) void gemm_hist_kernel(const float* __restrict__ x,
                                                        const float* __restrict__ W,
                                                        const float* __restrict__ a,
                                                        const int* __restrict__ ei) {
    __shared__ uint32_t Bhi[64 * 68];
    __shared__ uint32_t Blo[64 * 68];
    __shared__ float sa[2 * OUT_C];

    const int tid = threadIdx.x;

    if (blockIdx.x >= GEMM_BLOCKS) {
        // ---- histogram role ----
        int i = (blockIdx.x - GEMM_BLOCKS) * 256 + tid;
        const int stride = HIST_BLOCKS * 256;
        const int* col = ei + N_EDGES;
        for (; i < N_EDGES; i += stride)
            atomicAdd(&g_cnt[col[i]], 1);
        return;
    }

    // ---- GEMM role ----
    const int warp = tid >> 5;
    const int lane = tid & 31;
    const int qrow = lane >> 2;
    const int qcol = lane & 3;

    if (tid < 2 * OUT_C) sa[tid] = a[tid];

    const int row0 = blockIdx.x * 128 + warp * 16 + qrow;
    const int row1 = row0 + 8;
    const bool v0 = row0 < N_NODES;
    const bool v1 = row1 < N_NODES;
    const float* xr0 = x + (size_t)(v0 ? row0 : 0) * IN_C;
    const float* xr1 = x + (size_t)(v1 ? row1 : 0) * IN_C;

    float C[8][4];
#pragma unroll
    for (int nt = 0; nt < 8; nt++)
#pragma unroll
        for (int j = 0; j < 4; j++) C[nt][j] = 0.0f;

    for (int chunk = 0; chunk < 2; chunk++) {
        const int kbase = chunk * 128;
        __syncthreads();
        for (int w = tid; w < 64 * 64; w += 256) {
            int n  = w >> 6;
            int kw = w & 63;
            float2 v = *(const float2*)(W + (size_t)n * IN_C + kbase + kw * 2);
            uint32_t hi, lo;
            split2(v.x, v.y, hi, lo);
            Bhi[n * 68 + kw] = hi;
            Blo[n * 68 + kw] = lo;
        }
        __syncthreads();

#pragma unroll
        for (int s = 0; s < 8; s++) {
            const int k0 = kbase + s * 16;
            float2 a00 = *(const float2*)(xr0 + k0 + 2 * qcol);
            float2 a10 = *(const float2*)(xr1 + k0 + 2 * qcol);
            float2 a01 = *(const float2*)(xr0 + k0 + 8 + 2 * qcol);
            float2 a11 = *(const float2*)(xr1 + k0 + 8 + 2 * qcol);
            uint32_t ahi[4], alo[4];
            split2(a00.x, a00.y, ahi[0], alo[0]);
            split2(a10.x, a10.y, ahi[1], alo[1]);
            split2(a01.x, a01.y, ahi[2], alo[2]);
            split2(a11.x, a11.y, ahi[3], alo[3]);

            const int bb = qrow * 68 + s * 8 + qcol;
#pragma unroll
            for (int nt = 0; nt < 8; nt++) {
                const int nb = nt * 8 * 68 + bb;
                uint32_t bh0 = Bhi[nb], bh1 = Bhi[nb + 4];
                uint32_t bl0 = Blo[nb], bl1 = Blo[nb + 4];
                mma_bf16(C[nt], ahi, bh0, bh1);
                mma_bf16(C[nt], ahi, bl0, bl1);
                mma_bf16(C[nt], alo, bh0, bh1);
            }
        }
    }

    // epilogue: store h (fp16), fused attention scores (fp32)
    float si0 = 0.f, sj0 = 0.f, si1 = 0.f, sj1 = 0.f;
#pragma unroll
    for (int nt = 0; nt < 8; nt++) {
        int col = nt * 8 + 2 * qcol;
        int cw  = nt * 4 + qcol;
        if (v0) g_hh[((size_t)row0 << 5) + cw] = __floats2half2_rn(C[nt][0], C[nt][1]);
        if (v1) g_hh[((size_t)row1 << 5) + cw] = __floats2half2_rn(C[nt][2], C[nt][3]);
        si0 += C[nt][0] * sa[col]          + C[nt][1] * sa[col + 1];
        sj0 += C[nt][0] * sa[OUT_C + col]  + C[nt][1] * sa[OUT_C + col + 1];
        si1 += C[nt][2] * sa[col]          + C[nt][3] * sa[col + 1];
        sj1 += C[nt][2] * sa[OUT_C + col]  + C[nt][3] * sa[OUT_C + col + 1];
    }
#pragma unroll
    for (int off = 1; off < 4; off <<= 1) {
        si0 += __shfl_xor_sync(0xffffffffu, si0, off);
        sj0 += __shfl_xor_sync(0xffffffffu, sj0, off);
        si1 += __shfl_xor_sync(0xffffffffu, si1, off);
        sj1 += __shfl_xor_sync(0xffffffffu, sj1, off);
    }
    if (qcol == 0) {
        if (v0) { g_si[row0] = si0; g_sj[row0] = sj0; }
        if (v1) { g_si[row1] = si1; g_sj[row1] = sj1; }
    }
}

// ---------------- scan1: warp-shfl block scan (writes block totals to g_bsum) ----
__global__ __launch_bounds__(SCAN_BS) void scan1_kernel() {
    __shared__ int wsum[32];
    const int tid  = threadIdx.x;
    const int lane = tid & 31;
    const int wid  = tid >> 5;
    const int i    = blockIdx.x * SCAN_BS + tid;

    int v = (i < N_NODES) ? g_cnt[i] : 0;
    int incl = v;
#pragma unroll
    for (int off = 1; off < 32; off <<= 1) {
        int t = __shfl_up_sync(0xffffffffu, incl, off);
        if (lane >= off) incl += t;
    }
    if (lane == 31) wsum[wid] = incl;
    __syncthreads();
    if (wid == 0) {
        int w = wsum[lane];
        int s = w;
#pragma unroll
        for (int off = 1; off < 32; off <<= 1) {
            int t = __shfl_up_sync(0xffffffffu, s, off);
            if (lane >= off) s += t;
        }
        wsum[lane] = s - w;
    }
    __syncthreads();
    int excl = incl - v + wsum[wid];
    if (i < N_NODES) g_start[i] = excl;
    if (tid == SCAN_BS - 1) g_bsum[blockIdx.x] = excl + v;
}

// ---------------- scan3: add cross-block offset (each block sums its prefix) ----
__global__ __launch_bounds__(256) void scan3_kernel() {
    __shared__ int soff;
    const int b = (blockIdx.x * 256) >> 10;   // constant per block (256 | 1024)
    if (threadIdx.x < 32) {
        int sum = 0;
        for (int j = threadIdx.x; j < b; j += 32) sum += g_bsum[j];
#pragma unroll
        for (int off = 16; off > 0; off >>= 1)
            sum += __shfl_xor_sync(0xffffffffu, sum, off);
        if (threadIdx.x == 0) soff = sum;
    }
    __syncthreads();
    int i = blockIdx.x * 256 + threadIdx.x;
    if (i < N_NODES) g_start[i] += soff;
    if (i == 0) g_start[N_NODES] = NE_TOT;
}

// ---------------- place: CSR row indices only (cursor = decrementing g_cnt) -----
__global__ void place_kernel(const int* __restrict__ ei) {
    int i = blockIdx.x * blockDim.x + threadIdx.x;
    if (i >= NE_TOT) return;
    int r, c;
    if (i < N_EDGES) { r = ei[i]; c = ei[N_EDGES + i]; }
    else             { r = c = i - N_EDGES; }
    int off = atomicAdd(&g_cnt[c], -1) - 1;   // unique slot in [0, deg)
    g_csri[g_start[c] + off] = r;
}

// ---------------- gather: warp/node; lane-parallel p, broadcast accumulate ------
__global__ __launch_bounds__(256) void gather_kernel(float* __restrict__ out) {
    int node = (int)((blockIdx.x * 256 + threadIdx.x) >> 5);
    int lane = threadIdx.x & 31;
    if (node >= N_NODES) return;

    const int s = g_start[node];
    const int e = g_start[node + 1];
    const float si_c = g_si[node];

    float acc0 = 0.f, acc1 = 0.f, sp = 0.f;

    for (int base = s; base < e; base += 32) {
        const int n = e - base;
        const int cnt = n < 32 ? n : 32;

        // phase A: lane-parallel edge weights
        int   r = 0;
        float p = 0.f;
        if (lane < cnt) {
            r = g_csri[base + lane];
            float t = si_c + g_sj[r];
            t = fmaxf(t, NEG_SLOPE * t);     // leaky relu (slope < 1)
            p = __expf(t);                   // shift-free softmax weight
        }
        sp += p;

        // phase B: broadcast each edge, all lanes accumulate their channels
        int j = 0;
        for (; j + 4 <= cnt; j += 4) {
#pragma unroll
            for (int u = 0; u < 4; u++) {
                int   rj = __shfl_sync(0xffffffffu, r, j + u);
                float pj = __shfl_sync(0xffffffffu, p, j + u);
                float2 h2 = __half22float2(g_hh[((size_t)rj << 5) + lane]);
                acc0 = fmaf(pj, h2.x, acc0);
                acc1 = fmaf(pj, h2.y, acc1);
            }
        }
        for (; j < cnt; j++) {
            int   rj = __shfl_sync(0xffffffffu, r, j);
            float pj = __shfl_sync(0xffffffffu, p, j);
            float2 h2 = __half22float2(g_hh[((size_t)rj << 5) + lane]);
            acc0 = fmaf(pj, h2.x, acc0);
            acc1 = fmaf(pj, h2.y, acc1);
        }
    }

#pragma unroll
    for (int off = 16; off > 0; off >>= 1)
        sp += __shfl_xor_sync(0xffffffffu, sp, off);

    float inv = 1.0f / sp;                    // sp > 0: self-loop always present
    float2 o = make_float2(acc0 * inv, acc1 * inv);
    *(float2*)(out + ((size_t)node << 6) + (lane << 1)) = o;
}

// ---------------- launch ----------------
extern "C" void kernel_launch(void* const* d_in, const int* in_sizes, int n_in,
                              void* d_out, int out_size) {
    const float* x  = (const float*)d_in[0];
    const int*   ei = (const int*)  d_in[1];
    const float* W  = (const float*)d_in[2];
    const float* a  = (const float*)d_in[3];
    float* out = (float*)d_out;

    zero_kernel<<<(N_NODES + 255) / 256, 256>>>();
    gemm_hist_kernel<<<FUSED_BLOCKS, 256>>>(x, W, a, ei);
    scan1_kernel<<<SCAN_NB, SCAN_BS>>>();
    scan3_kernel<<<(N_NODES + 255) / 256, 256>>>();
    place_kernel<<<(NE_TOT + 255) / 256, 256>>>(ei);
    long long gthreads = (long long)N_NODES * 32;
    gather_kernel<<<(unsigned)((gthreads + 255) / 256), 256>>>(out);
}

// round 8
// speedup vs baseline: 1.1048x; 1.1048x over previous
#include <cuda_runtime.h>
#include <math.h>
#include <stdint.h>

#define N_NODES   100000
#define N_EDGES   3200000
#define NE_TOT    (N_EDGES + N_NODES)   // edges + self loops
#define IN_C      256
#define OUT_C     64
#define NEG_SLOPE 0.2f

#define SCAN_BS   1024
#define SCAN_NB   ((N_NODES + SCAN_BS - 1) / SCAN_BS)   // 98

#define GEMM_BLOCKS  782                 // ceil(100000 / 128)
#define HIST_BLOCKS  1568
#define FUSED_BLOCKS (GEMM_BLOCKS + HIST_BLOCKS)

// ---------------- scratch (static device globals; no allocation) ----------------
// g_cnt invariant: zero before every launch (static zero-init on first call;
// place_kernel decrements it back to exactly zero on every call).
__device__ float  g_h[(size_t)N_NODES * OUT_C];   // 25.6 MB: h = x @ W^T (fp32)
__device__ float  g_si[N_NODES];                  // h @ a_i
__device__ float  g_sj[N_NODES];                  // h @ a_j
__device__ int    g_cnt[N_NODES];                 // real-edge histogram / place cursor
__device__ int    g_start[N_NODES + 1];           // CSR offsets (deg incl. self-loop)
__device__ int    g_bsum[SCAN_NB];                // block sums for scan
__device__ float2 g_csr[NE_TOT];                  // {row (bitcast), p = exp(e)}

// ---------------- helpers ----------------
__device__ __forceinline__ void split2(float e, float o, uint32_t& hi, uint32_t& lo) {
    asm("cvt.rn.bf16x2.f32 %0, %1, %2;" : "=r"(hi) : "f"(o), "f"(e));
    float fe = __uint_as_float(hi << 16);
    float fo = __uint_as_float(hi & 0xffff0000u);
    asm("cvt.rn.bf16x2.f32 %0, %1, %2;" : "=r"(lo) : "f"(o - fo), "f"(e - fe));
}

__device__ __forceinline__ void mma_bf16(float* d, const uint32_t* a,
                                         uint32_t b0, uint32_t b1) {
    asm volatile(
        "mma.sync.aligned.m16n8k16.row.col.f32.bf16.bf16.f32 "
        "{%0,%1,%2,%3}, {%4,%5,%6,%7}, {%8,%9}, {%0,%1,%2,%3};"
        : "+f"(d[0]), "+f"(d[1]), "+f"(d[2]), "+f"(d[3])
        : "r"(a[0]), "r"(a[1]), "r"(a[2]), "r"(a[3]), "r"(b0), "r"(b1));
}

// ---------------- fused kernel: bf16-split TC GEMM + scores | histogram ----------
__global__ __launch_bounds__(256) void gemm_hist_kernel(const float* __restrict__ x,
                                                        const float* __restrict__ W,
                                                        const float* __restrict__ a,
                                                        const int* __restrict__ ei) {
    __shared__ uint32_t Bhi[64 * 68];
    __shared__ uint32_t Blo[64 * 68];
    __shared__ float sa[2 * OUT_C];

    const int tid = threadIdx.x;

    if (blockIdx.x >= GEMM_BLOCKS) {
        // ---- histogram role (real edges only; g_cnt starts at 0) ----
        int i = (blockIdx.x - GEMM_BLOCKS) * 256 + tid;
        const int stride = HIST_BLOCKS * 256;
        const int* col = ei + N_EDGES;
        for (; i < N_EDGES; i += stride)
            atomicAdd(&g_cnt[col[i]], 1);
        return;
    }

    // ---- GEMM role ----
    const int warp = tid >> 5;
    const int lane = tid & 31;
    const int qrow = lane >> 2;
    const int qcol = lane & 3;

    if (tid < 2 * OUT_C) sa[tid] = a[tid];

    const int row0 = blockIdx.x * 128 + warp * 16 + qrow;
    const int row1 = row0 + 8;
    const bool v0 = row0 < N_NODES;
    const bool v1 = row1 < N_NODES;
    const float* xr0 = x + (size_t)(v0 ? row0 : 0) * IN_C;
    const float* xr1 = x + (size_t)(v1 ? row1 : 0) * IN_C;

    float C[8][4];
#pragma unroll
    for (int nt = 0; nt < 8; nt++)
#pragma unroll
        for (int j = 0; j < 4; j++) C[nt][j] = 0.0f;

    for (int chunk = 0; chunk < 2; chunk++) {
        const int kbase = chunk * 128;
        __syncthreads();
        for (int w = tid; w < 64 * 64; w += 256) {
            int n  = w >> 6;
            int kw = w & 63;
            float2 v = *(const float2*)(W + (size_t)n * IN_C + kbase + kw * 2);
            uint32_t hi, lo;
            split2(v.x, v.y, hi, lo);
            Bhi[n * 68 + kw] = hi;
            Blo[n * 68 + kw] = lo;
        }
        __syncthreads();

#pragma unroll
        for (int s = 0; s < 8; s++) {
            const int k0 = kbase + s * 16;
            float2 a00 = *(const float2*)(xr0 + k0 + 2 * qcol);
            float2 a10 = *(const float2*)(xr1 + k0 + 2 * qcol);
            float2 a01 = *(const float2*)(xr0 + k0 + 8 + 2 * qcol);
            float2 a11 = *(const float2*)(xr1 + k0 + 8 + 2 * qcol);
            uint32_t ahi[4], alo[4];
            split2(a00.x, a00.y, ahi[0], alo[0]);
            split2(a10.x, a10.y, ahi[1], alo[1]);
            split2(a01.x, a01.y, ahi[2], alo[2]);
            split2(a11.x, a11.y, ahi[3], alo[3]);

            const int bb = qrow * 68 + s * 8 + qcol;
#pragma unroll
            for (int nt = 0; nt < 8; nt++) {
                const int nb = nt * 8 * 68 + bb;
                uint32_t bh0 = Bhi[nb], bh1 = Bhi[nb + 4];
                uint32_t bl0 = Blo[nb], bl1 = Blo[nb + 4];
                mma_bf16(C[nt], ahi, bh0, bh1);
                mma_bf16(C[nt], ahi, bl0, bl1);
                mma_bf16(C[nt], alo, bh0, bh1);
            }
        }
    }

    // epilogue: store h (fp32), fused attention scores
    float si0 = 0.f, sj0 = 0.f, si1 = 0.f, sj1 = 0.f;
#pragma unroll
    for (int nt = 0; nt < 8; nt++) {
        int col = nt * 8 + 2 * qcol;
        if (v0) *(float2*)(g_h + (size_t)row0 * OUT_C + col) = make_float2(C[nt][0], C[nt][1]);
        if (v1) *(float2*)(g_h + (size_t)row1 * OUT_C + col) = make_float2(C[nt][2], C[nt][3]);
        si0 += C[nt][0] * sa[col]          + C[nt][1] * sa[col + 1];
        sj0 += C[nt][0] * sa[OUT_C + col]  + C[nt][1] * sa[OUT_C + col + 1];
        si1 += C[nt][2] * sa[col]          + C[nt][3] * sa[col + 1];
        sj1 += C[nt][2] * sa[OUT_C + col]  + C[nt][3] * sa[OUT_C + col + 1];
    }
#pragma unroll
    for (int off = 1; off < 4; off <<= 1) {
        si0 += __shfl_xor_sync(0xffffffffu, si0, off);
        sj0 += __shfl_xor_sync(0xffffffffu, sj0, off);
        si1 += __shfl_xor_sync(0xffffffffu, si1, off);
        sj1 += __shfl_xor_sync(0xffffffffu, sj1, off);
    }
    if (qcol == 0) {
        if (v0) { g_si[row0] = si0; g_sj[row0] = sj0; }
        if (v1) { g_si[row1] = si1; g_sj[row1] = sj1; }
    }
}

// ---------------- scan1: warp-shfl block scan; degree = g_cnt + 1 (self loop) ----
__global__ __launch_bounds__(SCAN_BS) void scan1_kernel() {
    __shared__ int wsum[32];
    const int tid  = threadIdx.x;
    const int lane = tid & 31;
    const int wid  = tid >> 5;
    const int i    = blockIdx.x * SCAN_BS + tid;

    int v = (i < N_NODES) ? (g_cnt[i] + 1) : 0;   // +1: self loop
    int incl = v;
#pragma unroll
    for (int off = 1; off < 32; off <<= 1) {
        int t = __shfl_up_sync(0xffffffffu, incl, off);
        if (lane >= off) incl += t;
    }
    if (lane == 31) wsum[wid] = incl;
    __syncthreads();
    if (wid == 0) {
        int w = wsum[lane];
        int s = w;
#pragma unroll
        for (int off = 1; off < 32; off <<= 1) {
            int t = __shfl_up_sync(0xffffffffu, s, off);
            if (lane >= off) s += t;
        }
        wsum[lane] = s - w;
    }
    __syncthreads();
    int excl = incl - v + wsum[wid];
    if (i < N_NODES) g_start[i] = excl;
    if (tid == SCAN_BS - 1) g_bsum[blockIdx.x] = excl + v;
}

// ---------------- scan3: add cross-block offset (block sums its own prefix) ------
__global__ __launch_bounds__(256) void scan3_kernel() {
    __shared__ int soff;
    const int b = (blockIdx.x * 256) >> 10;
    if (threadIdx.x < 32) {
        int sum = 0;
        for (int j = threadIdx.x; j < b; j += 32) sum += g_bsum[j];
#pragma unroll
        for (int off = 16; off > 0; off >>= 1)
            sum += __shfl_xor_sync(0xffffffffu, sum, off);
        if (threadIdx.x == 0) soff = sum;
    }
    __syncthreads();
    int i = blockIdx.x * 256 + threadIdx.x;
    if (i < N_NODES) g_start[i] += soff;
    if (i == 0) g_start[N_NODES] = NE_TOT;
}

// ---------------- place: build CSR {row, p}; drains g_cnt back to zero -----------
__global__ void place_kernel(const int* __restrict__ ei) {
    int i = blockIdx.x * blockDim.x + threadIdx.x;
    if (i >= NE_TOT) return;
    int r, c, pos;
    if (i < N_EDGES) {
        r = ei[i]; c = ei[N_EDGES + i];
        int off = atomicAdd(&g_cnt[c], -1) - 1;   // unique slot in [0, deg_real)
        pos = g_start[c] + off;
    } else {
        r = c = i - N_EDGES;                      // self loop: fixed last slot
        pos = g_start[c + 1] - 1;
    }
    float e = g_si[c] + g_sj[r];
    e = (e >= 0.f) ? e : NEG_SLOPE * e;
    float p = expf(e);                            // shift-free softmax weight; bounded
    g_csr[pos] = make_float2(__int_as_float(r), p);
}

// ---------------- gather: warp/node; serial uniform loads, fused normalize -------
__global__ __launch_bounds__(256) void gather_kernel(float* __restrict__ out) {
    int node = (int)((blockIdx.x * 256 + threadIdx.x) >> 5);
    int lane = threadIdx.x & 31;
    if (node >= N_NODES) return;

    int s = g_start[node];
    int e = g_start[node + 1];

    float acc0 = 0.f, acc1 = 0.f, sp = 0.f;
#pragma unroll 4
    for (int k = s; k < e; k++) {
        float2 t = g_csr[k];                  // uniform within warp (broadcast)
        int   r  = __float_as_int(t.x);
        float p  = t.y;
        sp += p;
        float2 h2 = *(const float2*)(g_h + ((size_t)r << 6) + (lane << 1));
        acc0 = fmaf(p, h2.x, acc0);
        acc1 = fmaf(p, h2.y, acc1);
    }
    float inv = 1.0f / sp;                    // sp > 0: self-loop always present
    float2 o = make_float2(acc0 * inv, acc1 * inv);
    *(float2*)(out + ((size_t)node << 6) + (lane << 1)) = o;
}

// ---------------- launch ----------------
extern "C" void kernel_launch(void* const* d_in, const int* in_sizes, int n_in,
                              void* d_out, int out_size) {
    const float* x  = (const float*)d_in[0];
    const int*   ei = (const int*)  d_in[1];
    const float* W  = (const float*)d_in[2];
    const float* a  = (const float*)d_in[3];
    float* out = (float*)d_out;

    gemm_hist_kernel<<<FUSED_BLOCKS, 256>>>(x, W, a, ei);
    scan1_kernel<<<SCAN_NB, SCAN_BS>>>();
    scan3_kernel<<<(N_NODES + 255) / 256, 256>>>();
    place_kernel<<<(NE_TOT + 255) / 256, 256>>>(ei);
    long long gthreads = (long long)N_NODES * 32;
    gather_kernel<<<(unsigned)((gthreads + 255) / 256), 256>>>(out);
}

// round 9
// speedup vs baseline: 1.1889x; 1.0761x over previous
#include <cuda_runtime.h>
#include <math.h>
#include <stdint.h>

#define N_NODES   100000
#define N_EDGES   3200000
#define NE_TOT    (N_EDGES + N_NODES)   // edges + self loops
#define IN_C      256
#define OUT_C     64
#define NEG_SLOPE 0.2f

#define SCAN_BS   1024
#define SCAN_NB   ((N_NODES + SCAN_BS - 1) / SCAN_BS)   // 98

#define GEMM_BLOCKS  782                 // ceil(100000 / 128)
#define HIST_BLOCKS  1568
#define FUSED_BLOCKS (GEMM_BLOCKS + HIST_BLOCKS)

// ---------------- scratch (static device globals; no allocation) ----------------
// g_cnt invariant: zero before every launch (static zero-init on first call;
// scan3_kernel re-zeroes it every call after consuming it).
__device__ float              g_h[(size_t)N_NODES * OUT_C];  // 25.6 MB: h (fp32)
__device__ float              g_si[N_NODES];                 // h @ a_i
__device__ float              g_sj[N_NODES];                 // h @ a_j
__device__ int                g_cnt[N_NODES];                // real-edge histogram
__device__ int                g_start[N_NODES + 1];          // CSR offsets (incl. self-loop)
__device__ unsigned long long g_curs[N_NODES];               // {si bits, cursor=start+cnt}
__device__ int                g_bsum[SCAN_NB];               // block sums for scan
__device__ float2             g_csr[NE_TOT];                 // {row (bitcast), p = exp(e)}

// ---------------- helpers ----------------
__device__ __forceinline__ void split2(float e, float o, uint32_t& hi, uint32_t& lo) {
    asm("cvt.rn.bf16x2.f32 %0, %1, %2;" : "=r"(hi) : "f"(o), "f"(e));
    float fe = __uint_as_float(hi << 16);
    float fo = __uint_as_float(hi & 0xffff0000u);
    asm("cvt.rn.bf16x2.f32 %0, %1, %2;" : "=r"(lo) : "f"(o - fo), "f"(e - fe));
}

__device__ __forceinline__ void mma_bf16(float* d, const uint32_t* a,
                                         uint32_t b0, uint32_t b1) {
    asm volatile(
        "mma.sync.aligned.m16n8k16.row.col.f32.bf16.bf16.f32 "
        "{%0,%1,%2,%3}, {%4,%5,%6,%7}, {%8,%9}, {%0,%1,%2,%3};"
        : "+f"(d[0]), "+f"(d[1]), "+f"(d[2]), "+f"(d[3])
        : "r"(a[0]), "r"(a[1]), "r"(a[2]), "r"(a[3]), "r"(b0), "r"(b1));
}

// ---------------- fused kernel: bf16-split TC GEMM + scores | histogram ----------
__global__ __launch_bounds__(256) void gemm_hist_kernel(const float* __restrict__ x,
                                                        const float* __restrict__ W,
                                                        const float* __restrict__ a,
                                                        const int* __restrict__ ei) {
    __shared__ uint32_t Bhi[64 * 68];
    __shared__ uint32_t Blo[64 * 68];
    __shared__ float sa[2 * OUT_C];

    const int tid = threadIdx.x;

    if (blockIdx.x >= GEMM_BLOCKS) {
        // ---- histogram role (real edges only; g_cnt starts at 0) ----
        int i = (blockIdx.x - GEMM_BLOCKS) * 256 + tid;
        const int stride = HIST_BLOCKS * 256;
        const int* col = ei + N_EDGES;
        for (; i < N_EDGES; i += stride)
            atomicAdd(&g_cnt[col[i]], 1);
        return;
    }

    // ---- GEMM role ----
    const int warp = tid >> 5;
    const int lane = tid & 31;
    const int qrow = lane >> 2;
    const int qcol = lane & 3;

    if (tid < 2 * OUT_C) sa[tid] = a[tid];

    const int row0 = blockIdx.x * 128 + warp * 16 + qrow;
    const int row1 = row0 + 8;
    const bool v0 = row0 < N_NODES;
    const bool v1 = row1 < N_NODES;
    const float* xr0 = x + (size_t)(v0 ? row0 : 0) * IN_C;
    const float* xr1 = x + (size_t)(v1 ? row1 : 0) * IN_C;

    float C[8][4];
#pragma unroll
    for (int nt = 0; nt < 8; nt++)
#pragma unroll
        for (int j = 0; j < 4; j++) C[nt][j] = 0.0f;

    for (int chunk = 0; chunk < 2; chunk++) {
        const int kbase = chunk * 128;
        __syncthreads();
        for (int w = tid; w < 64 * 64; w += 256) {
            int n  = w >> 6;
            int kw = w & 63;
            float2 v = *(const float2*)(W + (size_t)n * IN_C + kbase + kw * 2);
            uint32_t hi, lo;
            split2(v.x, v.y, hi, lo);
            Bhi[n * 68 + kw] = hi;
            Blo[n * 68 + kw] = lo;
        }
        __syncthreads();

#pragma unroll
        for (int s = 0; s < 8; s++) {
            const int k0 = kbase + s * 16;
            float2 a00 = *(const float2*)(xr0 + k0 + 2 * qcol);
            float2 a10 = *(const float2*)(xr1 + k0 + 2 * qcol);
            float2 a01 = *(const float2*)(xr0 + k0 + 8 + 2 * qcol);
            float2 a11 = *(const float2*)(xr1 + k0 + 8 + 2 * qcol);
            uint32_t ahi[4], alo[4];
            split2(a00.x, a00.y, ahi[0], alo[0]);
            split2(a10.x, a10.y, ahi[1], alo[1]);
            split2(a01.x, a01.y, ahi[2], alo[2]);
            split2(a11.x, a11.y, ahi[3], alo[3]);

            const int bb = qrow * 68 + s * 8 + qcol;
#pragma unroll
            for (int nt = 0; nt < 8; nt++) {
                const int nb = nt * 8 * 68 + bb;
                uint32_t bh0 = Bhi[nb], bh1 = Bhi[nb + 4];
                uint32_t bl0 = Blo[nb], bl1 = Blo[nb + 4];
                mma_bf16(C[nt], ahi, bh0, bh1);
                mma_bf16(C[nt], ahi, bl0, bl1);
                mma_bf16(C[nt], alo, bh0, bh1);
            }
        }
    }

    // epilogue: store h (fp32), fused attention scores
    float si0 = 0.f, sj0 = 0.f, si1 = 0.f, sj1 = 0.f;
#pragma unroll
    for (int nt = 0; nt < 8; nt++) {
        int col = nt * 8 + 2 * qcol;
        if (v0) *(float2*)(g_h + (size_t)row0 * OUT_C + col) = make_float2(C[nt][0], C[nt][1]);
        if (v1) *(float2*)(g_h + (size_t)row1 * OUT_C + col) = make_float2(C[nt][2], C[nt][3]);
        si0 += C[nt][0] * sa[col]          + C[nt][1] * sa[col + 1];
        sj0 += C[nt][0] * sa[OUT_C + col]  + C[nt][1] * sa[OUT_C + col + 1];
        si1 += C[nt][2] * sa[col]          + C[nt][3] * sa[col + 1];
        sj1 += C[nt][2] * sa[OUT_C + col]  + C[nt][3] * sa[OUT_C + col + 1];
    }
#pragma unroll
    for (int off = 1; off < 4; off <<= 1) {
        si0 += __shfl_xor_sync(0xffffffffu, si0, off);
        sj0 += __shfl_xor_sync(0xffffffffu, sj0, off);
        si1 += __shfl_xor_sync(0xffffffffu, si1, off);
        sj1 += __shfl_xor_sync(0xffffffffu, sj1, off);
    }
    if (qcol == 0) {
        if (v0) { g_si[row0] = si0; g_sj[row0] = sj0; }
        if (v1) { g_si[row1] = si1; g_sj[row1] = sj1; }
    }
}

// ---------------- scan1: warp-shfl block scan; degree = g_cnt + 1 (self loop) ----
__global__ __launch_bounds__(SCAN_BS) void scan1_kernel() {
    __shared__ int wsum[32];
    const int tid  = threadIdx.x;
    const int lane = tid & 31;
    const int wid  = tid >> 5;
    const int i    = blockIdx.x * SCAN_BS + tid;

    int v = (i < N_NODES) ? (g_cnt[i] + 1) : 0;   // +1: self loop
    int incl = v;
#pragma unroll
    for (int off = 1; off < 32; off <<= 1) {
        int t = __shfl_up_sync(0xffffffffu, incl, off);
        if (lane >= off) incl += t;
    }
    if (lane == 31) wsum[wid] = incl;
    __syncthreads();
    if (wid == 0) {
        int w = wsum[lane];
        int s = w;
#pragma unroll
        for (int off = 1; off < 32; off <<= 1) {
            int t = __shfl_up_sync(0xffffffffu, s, off);
            if (lane >= off) s += t;
        }
        wsum[lane] = s - w;
    }
    __syncthreads();
    int excl = incl - v + wsum[wid];
    if (i < N_NODES) g_start[i] = excl;
    if (tid == SCAN_BS - 1) g_bsum[blockIdx.x] = excl + v;
}

// ---------------- scan3: finalize offsets, build packed cursors, reset g_cnt -----
__global__ __launch_bounds__(256) void scan3_kernel() {
    __shared__ int soff;
    const int b = (blockIdx.x * 256) >> 10;
    if (threadIdx.x < 32) {
        int sum = 0;
        for (int j = threadIdx.x; j < b; j += 32) sum += g_bsum[j];
#pragma unroll
        for (int off = 16; off > 0; off >>= 1)
            sum += __shfl_xor_sync(0xffffffffu, sum, off);
        if (threadIdx.x == 0) soff = sum;
    }
    __syncthreads();
    int i = blockIdx.x * 256 + threadIdx.x;
    if (i < N_NODES) {
        int start = g_start[i] + soff;
        g_start[i] = start;
        int cnt = g_cnt[i];
        g_cnt[i] = 0;                                     // restore hist invariant
        g_curs[i] = ((unsigned long long)__float_as_uint(g_si[i]) << 32)
                  | (unsigned int)(start + cnt);          // {si, absolute end cursor}
        if (i == 0) g_start[N_NODES] = NE_TOT;
    }
}

// ---------------- place: ONE 64-bit atomic yields {slot, si}; build CSR {r, p} ---
__global__ void place_kernel(const int* __restrict__ ei) {
    int i = blockIdx.x * blockDim.x + threadIdx.x;
    if (i >= NE_TOT) return;
    int r, pos;
    float si;
    if (i < N_EDGES) {
        r = ei[i];
        int c = ei[N_EDGES + i];
        // 64-bit -1: low word (cursor) decrements; never borrows since cursor >= 1
        unsigned long long old = atomicAdd(&g_curs[c], ~0ull);
        pos = (int)(unsigned int)old - 1;                 // unique slot in [start, start+cnt)
        si  = __uint_as_float((unsigned int)(old >> 32));
    } else {
        int c = i - N_EDGES;                              // self loop (coalesced reads)
        r   = c;
        pos = g_start[c + 1] - 1;                         // fixed last slot
        si  = g_si[c];
    }
    float e = si + g_sj[r];
    e = fmaxf(e, NEG_SLOPE * e);                          // leaky relu (slope < 1)
    float p = __expf(e);                                  // shift-free softmax weight
    g_csr[pos] = make_float2(__int_as_float(r), p);
}

// ---------------- gather: warp/node; serial uniform loads, fused normalize -------
__global__ __launch_bounds__(256) void gather_kernel(float* __restrict__ out) {
    int node = (int)((blockIdx.x * 256 + threadIdx.x) >> 5);
    int lane = threadIdx.x & 31;
    if (node >= N_NODES) return;

    int s = g_start[node];
    int e = g_start[node + 1];

    float acc0 = 0.f, acc1 = 0.f, sp = 0.f;
#pragma unroll 4
    for (int k = s; k < e; k++) {
        float2 t = g_csr[k];                  // uniform within warp (broadcast)
        int   r  = __float_as_int(t.x);
        float p  = t.y;
        sp += p;
        float2 h2 = *(const float2*)(g_h + ((size_t)r << 6) + (lane << 1));
        acc0 = fmaf(p, h2.x, acc0);
        acc1 = fmaf(p, h2.y, acc1);
    }
    float inv = 1.0f / sp;                    // sp > 0: self-loop always present
    float2 o = make_float2(acc0 * inv, acc1 * inv);
    *(float2*)(out + ((size_t)node << 6) + (lane << 1)) = o;
}

// ---------------- launch ----------------
extern "C" void kernel_launch(void* const* d_in, const int* in_sizes, int n_in,
                              void* d_out, int out_size) {
    const float* x  = (const float*)d_in[0];
    const int*   ei = (const int*)  d_in[1];
    const float* W  = (const float*)d_in[2];
    const float* a  = (const float*)d_in[3];
    float* out = (float*)d_out;

    gemm_hist_kernel<<<FUSED_BLOCKS, 256>>>(x, W, a, ei);
    scan1_kernel<<<SCAN_NB, SCAN_BS>>>();
    scan3_kernel<<<(N_NODES + 255) / 256, 256>>>();
    place_kernel<<<(NE_TOT + 255) / 256, 256>>>(ei);
    long long gthreads = (long long)N_NODES * 32;
    gather_kernel<<<(unsigned)((gthreads + 255) / 256), 256>>>(out);
}